// round 9
// baseline (speedup 1.0000x reference)
#include <cuda_runtime.h>
#include <cstddef>
#include <cstdint>

#define NB   4
#define TSZ  16
#define SRr  4
#define PD   1
#define SSn  11     // search span
#define SSC  9      // cropped span
#define WINs 26     // window size
#define WROW 27     // padded window row stride
#define SWt  0.1f
#define NMSE 176    // 11 sy * 16 rows

// ---------------- scratch (device globals; no allocation) ----------------
__device__ float g_ps1[NB*256*256], g_pd1[NB*256*256];
__device__ float g_ps2[NB*128*128], g_pd2[NB*128*128];
__device__ float g_ps3[NB*64*64],   g_pd3[NB*64*64];
__device__ float g_offA[NB*16*16*2];
__device__ float g_offB[NB*16*16*2];

// grid barrier (sense-reversal; even # barriers/launch -> replay-clean)
__device__ unsigned g_bar_count = 0;
__device__ unsigned g_bar_sense = 0;

// ---------------- shared memory -------------------------------------------
struct StepSh {
    float src[2][TSZ*TSZ];
    float win[2][WINs*WROW];
    float init[2][2];
    float part[SSn*SSn*17];
    float dist[SSn*SSn];
    float res[3];
};
struct PyrSh { float a[92*45]; float b[44*45]; };
union ShMem { StepSh st; PyrSh py; };

__device__ __forceinline__ unsigned long long umin64(unsigned long long a, unsigned long long b)
{ return a < b ? a : b; }

// ---------------- grid barrier (all blocks co-resident) --------------------
__device__ __forceinline__ void grid_barrier(int G, unsigned& local_sense)
{
    __syncthreads();
    if (threadIdx.x == 0) {
        local_sense ^= 1u;
        __threadfence();
        unsigned v = atomicAdd(&g_bar_count, 1u);
        if (v == (unsigned)(G - 1)) {
            g_bar_count = 0;
            __threadfence();
            *(volatile unsigned*)&g_bar_sense = local_sense;
        } else {
            while (*(volatile unsigned*)&g_bar_sense != local_sense)
                __nanosleep(64);
            __threadfence();
        }
    }
    __syncthreads();
}

// ---------------- pyramid: one 8x8 L3 tile of one image --------------------
__device__ void pyr_block(PyrSh& sh, int vb,
                          const float* __restrict__ src, const float* __restrict__ dst)
{
    const int im = vb >> 6;
    const int t  = vb & 63;
    const int bi = t >> 3, bj = t & 7;
    const int tid = threadIdx.x;

    const float* in = (im < NB) ? (src + (size_t)im * 512 * 512)
                                : (dst + (size_t)(im - NB) * 512 * 512);
    float* o1 = (im < NB) ? (g_ps1 + (size_t)im * 256 * 256) : (g_pd1 + (size_t)(im-NB) * 256 * 256);
    float* o2 = (im < NB) ? (g_ps2 + (size_t)im * 128 * 128) : (g_pd2 + (size_t)(im-NB) * 128 * 128);
    float* o3 = (im < NB) ? (g_ps3 + (size_t)im *  64 *  64) : (g_pd3 + (size_t)(im-NB) *  64 *  64);

    // separable taps: fused blur(5x5,zero-pad)+avgpool(2) = 6-tap outer product
    const float g0 = expf(-2.0f), g1 = expf(-0.5f), g2 = 1.0f;
    const float S  = g2 + 2.f*g1 + 2.f*g0;
    float ww[6];
    {
        const float ga[5] = {g0, g1, g2, g1, g0};
        ww[0] = 0.5f * ga[0] / S;
        #pragma unroll
        for (int u = 1; u < 5; u++) ww[u] = 0.5f * (ga[u] + ga[u-1]) / S;
        ww[5] = 0.5f * ga[4] / S;
    }

    const int yb = 64*bi - 14;
    const int xb = 64*bj - 14;

    // pass 1h: input -> tmp (92 x 44); interior fast path (no predicates)
    if (bi >= 1 && bi <= 6 && bj >= 1 && bj <= 6) {
        for (int id = tid; id < 92*44; id += 256) {
            int yy = id / 44, cx = id - yy*44;
            const float* row = in + (size_t)(yb + yy) * 512 + (xb + 2*cx);
            float v = 0.f;
            #pragma unroll
            for (int k = 0; k < 6; k++) v = fmaf(ww[k], row[k], v);
            sh.a[yy*45 + cx] = v;
        }
    } else {
        for (int id = tid; id < 92*44; id += 256) {
            int yy = id / 44, cx = id - yy*44;
            int gy = yb + yy;
            float v = 0.f;
            if (gy >= 0 && gy < 512) {
                const float* row = in + (size_t)gy * 512;
                int gx = xb + 2*cx;
                #pragma unroll
                for (int k = 0; k < 6; k++) {
                    int xx = gx + k;
                    if (xx >= 0 && xx < 512) v = fmaf(ww[k], row[xx], v);
                }
            }
            sh.a[yy*45 + cx] = v;
        }
    }
    __syncthreads();

    // pass 1v: -> level1 (44x44), write owned 32x32
    for (int id = tid; id < 44*44; id += 256) {
        int cy = id / 44, cx = id - cy*44;
        float v = 0.f;
        #pragma unroll
        for (int k = 0; k < 6; k++) v = fmaf(ww[k], sh.a[(2*cy + k)*45 + cx], v);
        int r1 = 32*bi - 6 + cy, c1 = 32*bj - 6 + cx;
        bool inimg = (r1 >= 0 && r1 < 256 && c1 >= 0 && c1 < 256);
        sh.b[cy*45 + cx] = inimg ? v : 0.f;
        if (cy >= 6 && cy < 38 && cx >= 6 && cx < 38)
            o1[(size_t)r1 * 256 + c1] = v;
    }
    __syncthreads();

    // pass 2h
    for (int id = tid; id < 44*20; id += 256) {
        int yy = id / 20, cx = id - yy*20;
        float v = 0.f;
        #pragma unroll
        for (int k = 0; k < 6; k++) v = fmaf(ww[k], sh.b[yy*45 + 2*cx + k], v);
        sh.a[yy*21 + cx] = v;
    }
    __syncthreads();

    // pass 2v: -> level2 (20x20), write owned 16x16
    for (int id = tid; id < 20*20; id += 256) {
        int cy = id / 20, cx = id - cy*20;
        float v = 0.f;
        #pragma unroll
        for (int k = 0; k < 6; k++) v = fmaf(ww[k], sh.a[(2*cy + k)*21 + cx], v);
        int r2 = 16*bi - 2 + cy, c2 = 16*bj - 2 + cx;
        bool inimg = (r2 >= 0 && r2 < 128 && c2 >= 0 && c2 < 128);
        sh.b[cy*21 + cx] = inimg ? v : 0.f;
        if (cy >= 2 && cy < 18 && cx >= 2 && cx < 18)
            o2[(size_t)r2 * 128 + c2] = v;
    }
    __syncthreads();

    // pass 3h
    for (int id = tid; id < 20*8; id += 256) {
        int yy = id >> 3, cx = id & 7;
        float v = 0.f;
        #pragma unroll
        for (int k = 0; k < 6; k++) v = fmaf(ww[k], sh.b[yy*21 + 2*cx + k], v);
        sh.a[yy*9 + cx] = v;
    }
    __syncthreads();

    // pass 3v: -> level3 (8x8)
    for (int id = tid; id < 64; id += 256) {
        int cy = id >> 3, cx = id & 7;
        float v = 0.f;
        #pragma unroll
        for (int k = 0; k < 6; k++) v = fmaf(ww[k], sh.a[(2*cy + k)*9 + cx], v);
        o3[(size_t)(8*bi + cy) * 64 + (8*bj + cx)] = v;
    }
    __syncthreads();
}

// ---------------- step helpers ---------------------------------------------
__device__ __forceinline__ void tile_coords(int tile, int nth, int& nb, int& ty, int& tx)
{
    tx = tile % nth;
    int t2 = tile / nth;
    ty = t2 % nth;
    nb = t2 / nth;
}

__device__ __forceinline__ void inherit_off(int nb, int ty, int tx, int H,
                                            const float* __restrict__ prev_off, int pnth,
                                            float& iyf, float& ixf)
{
    iyf = 0.f; ixf = 0.f;
    if (prev_off) {
        const float* p = prev_off + ((size_t)((nb*pnth + (ty>>1))*pnth + (tx>>1)))*2;
        float iy = (float)(ty*TSZ), ix = (float)(tx*TSZ);
        iyf = rintf(fminf(fmaxf(2.f*p[0] + iy, 0.f), (float)(H-TSZ)) - iy);
        ixf = rintf(fminf(fmaxf(2.f*p[1] + ix, 0.f), (float)(H-TSZ)) - ix);
    }
}

// gather one tile's window + src tile into buffer. FULL: all 256 threads.
// !FULL: warps 6,7 only (64 threads), used while warps 0-5 run MSE.
template<bool FULL>
__device__ void load_tile(StepSh& sh, int buf, int tile,
                          const float* __restrict__ src, const float* __restrict__ dst,
                          int H, int nth, const float* __restrict__ prev_off, int pnth)
{
    const int tid = threadIdx.x;
    const int w = tid >> 5, lane = tid & 31;
    int nb, ty, tx; tile_coords(tile, nth, nb, ty, tx);
    float iyf, ixf; inherit_off(nb, ty, tx, H, prev_off, pnth, iyf, ixf);
    const float* simg = src + (size_t)nb * H * H;
    const float* dimg = dst + (size_t)nb * H * H;
    const int y0 = ty*TSZ + (int)iyf - (SRr + PD);
    const int x0 = tx*TSZ + (int)ixf - (SRr + PD);
    const bool interior = (y0 >= 0 && x0 >= 0 && y0 + WINs <= H && x0 + WINs <= H);

    const int r0   = FULL ? w : (w - 6);
    const int rstp = FULL ? 8 : 2;
    if (lane < WINs) {
        if (interior) {
            const float* base = dimg + (size_t)y0 * H + x0 + lane;
            for (int r = r0; r < WINs; r += rstp)
                sh.win[buf][r*WROW + lane] = base[(size_t)r * H];
        } else {
            int xx = min(max(x0 + lane, 0), H - 1);
            for (int r = r0; r < WINs; r += rstp) {
                int yy = min(max(y0 + r, 0), H - 1);
                sh.win[buf][r*WROW + lane] = dimg[(size_t)yy * H + xx];
            }
        }
    }
    if (FULL) {
        int i = tid >> 4, j = tid & 15;
        sh.src[buf][tid] = simg[(size_t)(ty*TSZ + i) * H + tx*TSZ + j];
        if (tid == 0) { sh.init[buf][0] = iyf; sh.init[buf][1] = ixf; }
    } else {
        int base = tid - 192;
        #pragma unroll
        for (int k = 0; k < 4; k++) {
            int idx = base + 64*k;
            int i = idx >> 4, j = idx & 15;
            sh.src[buf][idx] = simg[(size_t)(ty*TSZ + i) * H + tx*TSZ + j];
        }
        if (tid == 192) { sh.init[buf][0] = iyf; sh.init[buf][1] = ixf; }
    }
}

// MSE partials, threads 0..175: (sy,i); window row + src row in registers
__device__ __forceinline__ void mse_tile(StepSh& sh, int buf)
{
    const int tid = threadIdx.x;
    const int sy = tid >> 4, i = tid & 15;
    float s[16], w[WINs];
    #pragma unroll
    for (int j = 0; j < 16; j++) s[j] = sh.src[buf][i*TSZ + j];
    const float* wr = sh.win[buf] + (sy + i)*WROW;
    #pragma unroll
    for (int j = 0; j < WINs; j++) w[j] = wr[j];
    float* pp = sh.part + sy*SSn*17 + i;
    #pragma unroll
    for (int sx = 0; sx < SSn; sx++) {
        float a0 = 0.f, a1 = 0.f;
        #pragma unroll
        for (int j = 0; j < 16; j += 2) {
            float d0 = w[sx + j]     - s[j];     a0 = fmaf(d0, d0, a0);
            float d1 = w[sx + j + 1] - s[j + 1]; a1 = fmaf(d1, d1, a1);
        }
        pp[sx*17] = a0 + a1;
    }
}

// reduce + argmin + subpixel. All threads enter (internal barrier).
__device__ void post_tile(StepSh& sh, int buf, float* out_off)
{
    const int tid = threadIdx.x;
    if (tid < SSn*SSn) {
        const float* p = sh.part + tid*17;
        float q0 = (p[0] + p[1])   + (p[2] + p[3]);
        float q1 = (p[4] + p[5])   + (p[6] + p[7]);
        float q2 = (p[8] + p[9])   + (p[10] + p[11]);
        float q3 = (p[12] + p[13]) + (p[14] + p[15]);
        float sum = (q0 + q1) + (q2 + q3);
        int sy = tid / SSn, sx = tid - (tid/SSn)*SSn;
        float ay = ((float)sy - (float)(SRr+PD)) / (float)SSn;
        float ax = ((float)sx - (float)(SRr+PD)) / (float)SSn;
        sh.dist[tid] = sum * (1.0f/256.0f) + SWt * (ay*ay + ax*ax);
    }
    __syncthreads();
    if (tid < 32) {
        unsigned long long key = ~0ULL;
        for (int k = tid; k < SSC*SSC; k += 32) {
            int py = k / SSC, px = k - (k/SSC)*SSC;
            float v = sh.dist[(py+PD)*SSn + px + PD];
            key = umin64(key, ((unsigned long long)__float_as_uint(v) << 32) | (unsigned)k);
        }
        #pragma unroll
        for (int o = 16; o > 0; o >>= 1)
            key = umin64(key, __shfl_down_sync(0xffffffffu, key, o));
        if (tid == 0) {
            int bk = (int)(key & 0xffffffffu);
            float best = __uint_as_float((unsigned)(key >> 32));
            int py = bk / SSC, px = bk - (bk/SSC)*SSC;
            float r[9];
            #pragma unroll
            for (int dy = 0; dy < 3; dy++)
                #pragma unroll
                for (int dx = 0; dx < 3; dx++)
                    r[dy*3+dx] = sh.dist[(py+PD-1+dy)*SSn + (px+PD-1+dx)];

            float a11 = (  r[0]-2.f*r[1]+r[2] + 2.f*r[3]-4.f*r[4]+2.f*r[5] +   r[6]-2.f*r[7]+r[8]) * 0.25f;
            float a22 = (  r[0]+2.f*r[1]+r[2] - 2.f*r[3]-4.f*r[4]-2.f*r[5] +   r[6]+2.f*r[7]+r[8]) * 0.25f;
            float a12 = (  r[0]        -r[2]                               -   r[6]         +r[8]) * 0.25f;
            float b1  = ( -r[0]        +r[2] - 2.f*r[3]        +2.f*r[5]   -   r[6]         +r[8]) * 0.125f;
            float b2  = ( -r[0]-2.f*r[1]-r[2]                              +   r[6]+2.f*r[7]+r[8]) * 0.125f;
            a11 = fmaxf(a11, 0.f);
            a22 = fmaxf(a22, 0.f);
            float det  = a11*a22 - a12*a12;
            float a12z = (det < 0.f) ? 0.f : a12;
            float mux  = -(a22*b1 - a12z*b2) / det;
            float muy  = -(a11*b2 - a12z*b1) / det;
            float mlen = sqrtf(muy*muy + mux*mux);
            float dxs  = (mlen < 1.f) ? mux : 0.f;
            float dys  = (mlen < 1.f) ? muy : 0.f;

            float offy = sh.init[buf][0] + (float)(py - SRr) + dys;
            float offx = sh.init[buf][1] + (float)(px - SRr) + dxs;
            if (out_off) { out_off[0] = offy; out_off[1] = offx; }
            sh.res[0] = offy; sh.res[1] = offx; sh.res[2] = best;
        }
    }
}

// one alignment level: pipelined tile loop (load t+1 under MSE of t)
__device__ void step_level(StepSh& sh, int G, int nTiles,
                           const float* __restrict__ src, const float* __restrict__ dst,
                           int H, int nth,
                           const float* __restrict__ prev_off, int pnth,
                           float* __restrict__ out_off, float* __restrict__ out_pix)
{
    if ((int)blockIdx.x >= nTiles) return;
    const int tid = threadIdx.x;
    load_tile<true>(sh, 0, blockIdx.x, src, dst, H, nth, prev_off, pnth);
    int p = 0;
    for (int t = blockIdx.x; t < nTiles; t += G, p ^= 1) {
        __syncthreads();                                   // buf[p] ready, part free
        if (tid < NMSE)
            mse_tile(sh, p);
        else if (tid >= 192 && t + G < nTiles)
            load_tile<false>(sh, p ^ 1, t + G, src, dst, H, nth, prev_off, pnth);
        __syncthreads();                                   // part ready
        post_tile(sh, p, out_off ? out_off + (size_t)t*2 : nullptr);
        if (out_pix) {
            __syncthreads();                               // res ready
            int nb, ty, tx; tile_coords(t, nth, nb, ty, tx);
            float2 ov = make_float2(sh.res[0], sh.res[1]);
            int i = tid >> 4, j = tid & 15;
            int y = ty*TSZ + i, x = tx*TSZ + j;
            size_t pix = ((size_t)nb * H + y) * H + x;
            reinterpret_cast<float2*>(out_pix)[pix] = ov;
            out_pix[(size_t)NB * H * H * 2 + pix] = sh.res[2];
        }
    }
}

// ---------------- persistent mega-kernel ------------------------------------
__global__ void __launch_bounds__(256)
align_kernel(const float* __restrict__ src, const float* __restrict__ dst,
             float* __restrict__ out, int G)
{
    __shared__ ShMem sh;
    unsigned local_sense = 0;

    for (int vb = blockIdx.x; vb < 8*64; vb += G)
        pyr_block(sh.py, vb, src, dst);
    grid_barrier(G, local_sense);

    step_level(sh.st, G, NB*4*4,   g_ps3, g_pd3,  64,  4, nullptr, 0,  g_offA, nullptr);
    grid_barrier(G, local_sense);

    step_level(sh.st, G, NB*8*8,   g_ps2, g_pd2, 128,  8, g_offA,  4,  g_offB, nullptr);
    grid_barrier(G, local_sense);

    step_level(sh.st, G, NB*16*16, g_ps1, g_pd1, 256, 16, g_offB,  8,  g_offA, nullptr);
    grid_barrier(G, local_sense);

    step_level(sh.st, G, NB*32*32, src, dst, 512, 32, g_offA, 16,  nullptr, out);
}

// ---------------- launch ---------------------------------------------------
extern "C" void kernel_launch(void* const* d_in, const int* in_sizes, int n_in,
                              void* d_out, int out_size)
{
    const float* src = (const float*)d_in[0];
    const float* dst = (const float*)d_in[1];
    float* out = (float*)d_out;

    static int G = 0;
    if (G == 0) {
        int nsm = 0, bpm = 0;
        cudaDeviceGetAttribute(&nsm, cudaDevAttrMultiProcessorCount, 0);
        cudaOccupancyMaxActiveBlocksPerMultiprocessor(&bpm, align_kernel, 256, 0);
        if (bpm < 1) bpm = 1;
        G = nsm * bpm;
    }

    align_kernel<<<G, 256>>>(src, dst, out, G);
}

// round 13
// speedup vs baseline: 1.5630x; 1.5630x over previous
#include <cuda_runtime.h>
#include <cstddef>
#include <cstdint>

#define NB   4
#define TSZ  16
#define SRr  4
#define PD   1
#define SSn  11     // search span
#define SSC  9      // cropped span
#define WINs 26     // window size
#define WROW 27     // padded window row stride
#define SWt  0.1f
#define NMSE 176    // 11 sy * 16 rows

// ---------------- scratch (device globals; no allocation) ----------------
__device__ float g_ps1[NB*256*256], g_pd1[NB*256*256];
__device__ float g_ps2[NB*128*128], g_pd2[NB*128*128];
__device__ float g_ps3[NB*64*64],   g_pd3[NB*64*64];
__device__ float g_offA[NB*16*16*2];
__device__ float g_offB[NB*16*16*2];

// grid barrier (sense-reversal; even # barriers/launch -> replay-clean)
__device__ unsigned g_bar_count = 0;
__device__ unsigned g_bar_sense = 0;

// ---------------- shared memory -------------------------------------------
struct StepSh {
    float src[2][TSZ*TSZ];
    float win[2][WINs*WROW];
    float init[2][2];
    float part[SSn*SSn*17];
    float dist[SSn*SSn];
    float res[3];
};
struct PyrSh { float a[92*45]; float b[44*45]; };
union ShMem { StepSh st; PyrSh py; };

__device__ __forceinline__ unsigned long long umin64(unsigned long long a, unsigned long long b)
{ return a < b ? a : b; }

// ---------------- cp.async helpers -----------------------------------------
__device__ __forceinline__ void cp_async4(void* smem, const void* g)
{
    unsigned sa = (unsigned)__cvta_generic_to_shared(smem);
    asm volatile("cp.async.ca.shared.global [%0], [%1], 4;" :: "r"(sa), "l"(g));
}
__device__ __forceinline__ void cp_commit()
{ asm volatile("cp.async.commit_group;"); }
template<int N> __device__ __forceinline__ void cp_wait()
{ asm volatile("cp.async.wait_group %0;" :: "n"(N)); }

// ---------------- grid barrier (all blocks co-resident) --------------------
__device__ __forceinline__ void grid_barrier(int G, unsigned& local_sense)
{
    __syncthreads();
    if (threadIdx.x == 0) {
        local_sense ^= 1u;
        __threadfence();
        unsigned v = atomicAdd(&g_bar_count, 1u);
        if (v == (unsigned)(G - 1)) {
            g_bar_count = 0;
            __threadfence();
            *(volatile unsigned*)&g_bar_sense = local_sense;
        } else {
            while (*(volatile unsigned*)&g_bar_sense != local_sense)
                __nanosleep(64);
            __threadfence();
        }
    }
    __syncthreads();
}

// ---------------- pyramid: one 8x8 L3 tile of one image --------------------
__device__ void pyr_block(PyrSh& sh, int vb,
                          const float* __restrict__ src, const float* __restrict__ dst)
{
    const int im = vb >> 6;
    const int t  = vb & 63;
    const int bi = t >> 3, bj = t & 7;
    const int tid = threadIdx.x;

    const float* in = (im < NB) ? (src + (size_t)im * 512 * 512)
                                : (dst + (size_t)(im - NB) * 512 * 512);
    float* o1 = (im < NB) ? (g_ps1 + (size_t)im * 256 * 256) : (g_pd1 + (size_t)(im-NB) * 256 * 256);
    float* o2 = (im < NB) ? (g_ps2 + (size_t)im * 128 * 128) : (g_pd2 + (size_t)(im-NB) * 128 * 128);
    float* o3 = (im < NB) ? (g_ps3 + (size_t)im *  64 *  64) : (g_pd3 + (size_t)(im-NB) *  64 *  64);

    // separable taps: fused blur(5x5,zero-pad)+avgpool(2) = 6-tap outer product
    const float g0 = expf(-2.0f), g1 = expf(-0.5f), g2 = 1.0f;
    const float S  = g2 + 2.f*g1 + 2.f*g0;
    float ww[6];
    {
        const float ga[5] = {g0, g1, g2, g1, g0};
        ww[0] = 0.5f * ga[0] / S;
        #pragma unroll
        for (int u = 1; u < 5; u++) ww[u] = 0.5f * (ga[u] + ga[u-1]) / S;
        ww[5] = 0.5f * ga[4] / S;
    }

    const int yb = 64*bi - 14;
    const int xb = 64*bj - 14;

    // pass 1h: input -> tmp (92 x 44); interior fast path
    if (bi >= 1 && bi <= 6 && bj >= 1 && bj <= 6) {
        for (int id = tid; id < 92*44; id += 256) {
            int yy = id / 44, cx = id - yy*44;
            const float* row = in + (size_t)(yb + yy) * 512 + (xb + 2*cx);
            float v = 0.f;
            #pragma unroll
            for (int k = 0; k < 6; k++) v = fmaf(ww[k], row[k], v);
            sh.a[yy*45 + cx] = v;
        }
    } else {
        for (int id = tid; id < 92*44; id += 256) {
            int yy = id / 44, cx = id - yy*44;
            int gy = yb + yy;
            float v = 0.f;
            if (gy >= 0 && gy < 512) {
                const float* row = in + (size_t)gy * 512;
                int gx = xb + 2*cx;
                #pragma unroll
                for (int k = 0; k < 6; k++) {
                    int xx = gx + k;
                    if (xx >= 0 && xx < 512) v = fmaf(ww[k], row[xx], v);
                }
            }
            sh.a[yy*45 + cx] = v;
        }
    }
    __syncthreads();

    // pass 1v: -> level1 (44x44), write owned 32x32
    for (int id = tid; id < 44*44; id += 256) {
        int cy = id / 44, cx = id - cy*44;
        float v = 0.f;
        #pragma unroll
        for (int k = 0; k < 6; k++) v = fmaf(ww[k], sh.a[(2*cy + k)*45 + cx], v);
        int r1 = 32*bi - 6 + cy, c1 = 32*bj - 6 + cx;
        bool inimg = (r1 >= 0 && r1 < 256 && c1 >= 0 && c1 < 256);
        sh.b[cy*45 + cx] = inimg ? v : 0.f;
        if (cy >= 6 && cy < 38 && cx >= 6 && cx < 38)
            o1[(size_t)r1 * 256 + c1] = v;
    }
    __syncthreads();

    // pass 2h
    for (int id = tid; id < 44*20; id += 256) {
        int yy = id / 20, cx = id - yy*20;
        float v = 0.f;
        #pragma unroll
        for (int k = 0; k < 6; k++) v = fmaf(ww[k], sh.b[yy*45 + 2*cx + k], v);
        sh.a[yy*21 + cx] = v;
    }
    __syncthreads();

    // pass 2v: -> level2 (20x20), write owned 16x16
    for (int id = tid; id < 20*20; id += 256) {
        int cy = id / 20, cx = id - cy*20;
        float v = 0.f;
        #pragma unroll
        for (int k = 0; k < 6; k++) v = fmaf(ww[k], sh.a[(2*cy + k)*21 + cx], v);
        int r2 = 16*bi - 2 + cy, c2 = 16*bj - 2 + cx;
        bool inimg = (r2 >= 0 && r2 < 128 && c2 >= 0 && c2 < 128);
        sh.b[cy*21 + cx] = inimg ? v : 0.f;
        if (cy >= 2 && cy < 18 && cx >= 2 && cx < 18)
            o2[(size_t)r2 * 128 + c2] = v;
    }
    __syncthreads();

    // pass 3h
    for (int id = tid; id < 20*8; id += 256) {
        int yy = id >> 3, cx = id & 7;
        float v = 0.f;
        #pragma unroll
        for (int k = 0; k < 6; k++) v = fmaf(ww[k], sh.b[yy*21 + 2*cx + k], v);
        sh.a[yy*9 + cx] = v;
    }
    __syncthreads();

    // pass 3v: -> level3 (8x8)
    for (int id = tid; id < 64; id += 256) {
        int cy = id >> 3, cx = id & 7;
        float v = 0.f;
        #pragma unroll
        for (int k = 0; k < 6; k++) v = fmaf(ww[k], sh.a[(2*cy + k)*9 + cx], v);
        o3[(size_t)(8*bi + cy) * 64 + (8*bj + cx)] = v;
    }
    __syncthreads();
}

// ---------------- step helpers ---------------------------------------------
__device__ __forceinline__ void tile_coords(int tile, int nth, int& nb, int& ty, int& tx)
{
    tx = tile % nth;
    int t2 = tile / nth;
    ty = t2 % nth;
    nb = t2 / nth;
}

__device__ __forceinline__ void inherit_off(int nb, int ty, int tx, int H,
                                            const float* __restrict__ prev_off, int pnth,
                                            float& iyf, float& ixf)
{
    iyf = 0.f; ixf = 0.f;
    if (prev_off) {
        const float* p = prev_off + ((size_t)((nb*pnth + (ty>>1))*pnth + (tx>>1)))*2;
        float iy = (float)(ty*TSZ), ix = (float)(tx*TSZ);
        iyf = rintf(fminf(fmaxf(2.f*p[0] + iy, 0.f), (float)(H-TSZ)) - iy);
        ixf = rintf(fminf(fmaxf(2.f*p[1] + ix, 0.f), (float)(H-TSZ)) - ix);
    }
}

// issue async copies for one tile's window + src tile into buffer `buf`.
// All 256 threads; ~4 LDGSTS each; returns immediately (no stall).
__device__ void issue_load(StepSh& sh, int buf, int tile,
                           const float* __restrict__ src, const float* __restrict__ dst,
                           int H, int nth, const float* __restrict__ prev_off, int pnth)
{
    const int tid = threadIdx.x;
    const int w = tid >> 5, lane = tid & 31;
    int nb, ty, tx; tile_coords(tile, nth, nb, ty, tx);
    float iyf, ixf; inherit_off(nb, ty, tx, H, prev_off, pnth, iyf, ixf);
    const float* simg = src + (size_t)nb * H * H;
    const float* dimg = dst + (size_t)nb * H * H;
    const int y0 = ty*TSZ + (int)iyf - (SRr + PD);
    const int x0 = tx*TSZ + (int)ixf - (SRr + PD);

    if (lane < WINs) {
        int xx = min(max(x0 + lane, 0), H - 1);
        #pragma unroll
        for (int rr = 0; rr < 4; rr++) {
            int r = w + 8*rr;
            if (r < WINs) {
                int yy = min(max(y0 + r, 0), H - 1);
                cp_async4(&sh.win[buf][r*WROW + lane], dimg + (size_t)yy * H + xx);
            }
        }
    }
    {
        int i = tid >> 4, j = tid & 15;
        cp_async4(&sh.src[buf][tid], simg + (size_t)(ty*TSZ + i) * H + tx*TSZ + j);
    }
    if (tid == 0) { sh.init[buf][0] = iyf; sh.init[buf][1] = ixf; }
}

// MSE partials, threads 0..175: (sy,i); window row + src row in registers
__device__ __forceinline__ void mse_tile(StepSh& sh, int buf)
{
    const int tid = threadIdx.x;
    const int sy = tid >> 4, i = tid & 15;
    float s[16], w[WINs];
    #pragma unroll
    for (int j = 0; j < 16; j++) s[j] = sh.src[buf][i*TSZ + j];
    const float* wr = sh.win[buf] + (sy + i)*WROW;
    #pragma unroll
    for (int j = 0; j < WINs; j++) w[j] = wr[j];
    float* pp = sh.part + sy*SSn*17 + i;
    #pragma unroll
    for (int sx = 0; sx < SSn; sx++) {
        float a0 = 0.f, a1 = 0.f;
        #pragma unroll
        for (int j = 0; j < 16; j += 2) {
            float d0 = w[sx + j]     - s[j];     a0 = fmaf(d0, d0, a0);
            float d1 = w[sx + j + 1] - s[j + 1]; a1 = fmaf(d1, d1, a1);
        }
        pp[sx*17] = a0 + a1;
    }
}

// reduce + argmin + subpixel. All threads enter (internal barrier).
__device__ void post_tile(StepSh& sh, int buf, float* out_off)
{
    const int tid = threadIdx.x;
    if (tid < SSn*SSn) {
        const float* p = sh.part + tid*17;
        float q0 = (p[0] + p[1])   + (p[2] + p[3]);
        float q1 = (p[4] + p[5])   + (p[6] + p[7]);
        float q2 = (p[8] + p[9])   + (p[10] + p[11]);
        float q3 = (p[12] + p[13]) + (p[14] + p[15]);
        float sum = (q0 + q1) + (q2 + q3);
        int sy = tid / SSn, sx = tid - (tid/SSn)*SSn;
        float ay = ((float)sy - (float)(SRr+PD)) / (float)SSn;
        float ax = ((float)sx - (float)(SRr+PD)) / (float)SSn;
        sh.dist[tid] = sum * (1.0f/256.0f) + SWt * (ay*ay + ax*ax);
    }
    __syncthreads();
    if (tid < 32) {
        unsigned long long key = ~0ULL;
        for (int k = tid; k < SSC*SSC; k += 32) {
            int py = k / SSC, px = k - (k/SSC)*SSC;
            float v = sh.dist[(py+PD)*SSn + px + PD];
            key = umin64(key, ((unsigned long long)__float_as_uint(v) << 32) | (unsigned)k);
        }
        #pragma unroll
        for (int o = 16; o > 0; o >>= 1)
            key = umin64(key, __shfl_down_sync(0xffffffffu, key, o));
        if (tid == 0) {
            int bk = (int)(key & 0xffffffffu);
            float best = __uint_as_float((unsigned)(key >> 32));
            int py = bk / SSC, px = bk - (bk/SSC)*SSC;
            float r[9];
            #pragma unroll
            for (int dy = 0; dy < 3; dy++)
                #pragma unroll
                for (int dx = 0; dx < 3; dx++)
                    r[dy*3+dx] = sh.dist[(py+PD-1+dy)*SSn + (px+PD-1+dx)];

            float a11 = (  r[0]-2.f*r[1]+r[2] + 2.f*r[3]-4.f*r[4]+2.f*r[5] +   r[6]-2.f*r[7]+r[8]) * 0.25f;
            float a22 = (  r[0]+2.f*r[1]+r[2] - 2.f*r[3]-4.f*r[4]-2.f*r[5] +   r[6]+2.f*r[7]+r[8]) * 0.25f;
            float a12 = (  r[0]        -r[2]                               -   r[6]         +r[8]) * 0.25f;
            float b1  = ( -r[0]        +r[2] - 2.f*r[3]        +2.f*r[5]   -   r[6]         +r[8]) * 0.125f;
            float b2  = ( -r[0]-2.f*r[1]-r[2]                              +   r[6]+2.f*r[7]+r[8]) * 0.125f;
            a11 = fmaxf(a11, 0.f);
            a22 = fmaxf(a22, 0.f);
            float det  = a11*a22 - a12*a12;
            float a12z = (det < 0.f) ? 0.f : a12;
            float mux  = -(a22*b1 - a12z*b2) / det;
            float muy  = -(a11*b2 - a12z*b1) / det;
            float mlen = sqrtf(muy*muy + mux*mux);
            float dxs  = (mlen < 1.f) ? mux : 0.f;
            float dys  = (mlen < 1.f) ? muy : 0.f;

            float offy = sh.init[buf][0] + (float)(py - SRr) + dys;
            float offx = sh.init[buf][1] + (float)(px - SRr) + dxs;
            if (out_off) { out_off[0] = offy; out_off[1] = offx; }
            sh.res[0] = offy; sh.res[1] = offx; sh.res[2] = best;
        }
    }
}

// one alignment level: cp.async double-buffered tile loop
__device__ void step_level(StepSh& sh, int G, int nTiles,
                           const float* __restrict__ src, const float* __restrict__ dst,
                           int H, int nth,
                           const float* __restrict__ prev_off, int pnth,
                           float* __restrict__ out_off, float* __restrict__ out_pix)
{
    if ((int)blockIdx.x >= nTiles) return;
    const int tid = threadIdx.x;

    issue_load(sh, 0, blockIdx.x, src, dst, H, nth, prev_off, pnth);
    cp_commit();

    int p = 0;
    for (int t = blockIdx.x; t < nTiles; t += G, p ^= 1) {
        if (t + G < nTiles) {
            issue_load(sh, p ^ 1, t + G, src, dst, H, nth, prev_off, pnth);
            cp_commit();
            cp_wait<1>();     // group for current tile done (FIFO)
        } else {
            cp_wait<0>();
        }
        __syncthreads();                                   // buf[p] visible
        if (tid < NMSE) mse_tile(sh, p);
        __syncthreads();                                   // part ready
        post_tile(sh, p, out_off ? out_off + (size_t)t*2 : nullptr);
        if (out_pix) {
            __syncthreads();                               // res ready
            int nb, ty, tx; tile_coords(t, nth, nb, ty, tx);
            float2 ov = make_float2(sh.res[0], sh.res[1]);
            int i = tid >> 4, j = tid & 15;
            int y = ty*TSZ + i, x = tx*TSZ + j;
            size_t pix = ((size_t)nb * H + y) * H + x;
            reinterpret_cast<float2*>(out_pix)[pix] = ov;
            out_pix[(size_t)NB * H * H * 2 + pix] = sh.res[2];
        }
    }
}

// ---------------- persistent mega-kernel ------------------------------------
__global__ void __launch_bounds__(256)
align_kernel(const float* __restrict__ src, const float* __restrict__ dst,
             float* __restrict__ out, int G)
{
    __shared__ ShMem sh;
    unsigned local_sense = 0;

    for (int vb = blockIdx.x; vb < 8*64; vb += G)
        pyr_block(sh.py, vb, src, dst);
    grid_barrier(G, local_sense);

    step_level(sh.st, G, NB*4*4,   g_ps3, g_pd3,  64,  4, nullptr, 0,  g_offA, nullptr);
    grid_barrier(G, local_sense);

    step_level(sh.st, G, NB*8*8,   g_ps2, g_pd2, 128,  8, g_offA,  4,  g_offB, nullptr);
    grid_barrier(G, local_sense);

    step_level(sh.st, G, NB*16*16, g_ps1, g_pd1, 256, 16, g_offB,  8,  g_offA, nullptr);
    grid_barrier(G, local_sense);

    step_level(sh.st, G, NB*32*32, src, dst, 512, 32, g_offA, 16,  nullptr, out);
}

// ---------------- launch ---------------------------------------------------
extern "C" void kernel_launch(void* const* d_in, const int* in_sizes, int n_in,
                              void* d_out, int out_size)
{
    const float* src = (const float*)d_in[0];
    const float* dst = (const float*)d_in[1];
    float* out = (float*)d_out;

    static int G = 0;
    if (G == 0) {
        int nsm = 0, bpm = 0;
        cudaDeviceGetAttribute(&nsm, cudaDevAttrMultiProcessorCount, 0);
        cudaOccupancyMaxActiveBlocksPerMultiprocessor(&bpm, align_kernel, 256, 0);
        if (bpm < 1) bpm = 1;
        G = nsm * bpm;
    }

    align_kernel<<<G, 256>>>(src, dst, out, G);
}